// round 1
// baseline (speedup 1.0000x reference)
#include <cuda_runtime.h>

#define BB 16384
#define KK 4096
#define CHUNKS 128          // row-chunks for column passes
#define RPB (BB / CHUNKS)   // 128 rows per chunk
#define CPB 1024            // columns per colpass block (256 thr * float4)
#define NTHR 256
#define INV_EPS 20.0f       // 1/0.05

// ---- scratch (device globals; no allocation) ----
__device__ float    g_part_m[CHUNKS][KK];
__device__ float    g_part_s[CHUNKS][KK];
__device__ float    g_a[KK];     // a[k] = 1/s[k]
__device__ float    g_t[BB];     // stored as reciprocal: d[b] = 1/t[b]
__device__ unsigned g_Mbits;     // order-encoded global max

__device__ __forceinline__ unsigned enc_f(float x) {
    unsigned u = __float_as_uint(x);
    return (u & 0x80000000u) ? ~u : (u | 0x80000000u);
}
__device__ __forceinline__ float dec_f(unsigned u) {
    return (u & 0x80000000u) ? __uint_as_float(u & 0x7FFFFFFFu)
                             : __uint_as_float(~u);
}

__device__ __forceinline__ float blockSum(float v, float* red) {
    #pragma unroll
    for (int o = 16; o; o >>= 1) v += __shfl_xor_sync(0xffffffffu, v, o);
    int w = threadIdx.x >> 5;
    if ((threadIdx.x & 31) == 0) red[w] = v;
    __syncthreads();
    if (threadIdx.x == 0) {
        float r = red[0] + red[1] + red[2] + red[3]
                + red[4] + red[5] + red[6] + red[7];
        red[0] = r;
    }
    __syncthreads();
    float r = red[0];
    __syncthreads();
    return r;
}

__global__ void k_init() { g_Mbits = 0u; }

// Pass 1: per-chunk online column (over b) sums of exp with local max,
// plus global max via atomicMax.
__global__ __launch_bounds__(NTHR) void k_pass1(const float* __restrict__ x) {
    const int    k0   = blockIdx.x * CPB + threadIdx.x * 4;
    const size_t base = (size_t)blockIdx.y * RPB * KK + k0;
    const float  NEGINF = __int_as_float(0xff800000);
    float m0 = NEGINF, m1 = NEGINF, m2 = NEGINF, m3 = NEGINF;
    float s0 = 0.f, s1 = 0.f, s2 = 0.f, s3 = 0.f;

    #pragma unroll 4
    for (int r = 0; r < RPB; r++) {
        float4 v = __ldg((const float4*)(x + base + (size_t)r * KK));
        if (v.x > m0) { s0 = s0 * __expf((m0 - v.x) * INV_EPS) + 1.0f; m0 = v.x; }
        else          { s0 += __expf((v.x - m0) * INV_EPS); }
        if (v.y > m1) { s1 = s1 * __expf((m1 - v.y) * INV_EPS) + 1.0f; m1 = v.y; }
        else          { s1 += __expf((v.y - m1) * INV_EPS); }
        if (v.z > m2) { s2 = s2 * __expf((m2 - v.z) * INV_EPS) + 1.0f; m2 = v.z; }
        else          { s2 += __expf((v.z - m2) * INV_EPS); }
        if (v.w > m3) { s3 = s3 * __expf((m3 - v.w) * INV_EPS) + 1.0f; m3 = v.w; }
        else          { s3 += __expf((v.w - m3) * INV_EPS); }
    }
    int c = blockIdx.y;
    *(float4*)&g_part_m[c][k0] = make_float4(m0, m1, m2, m3);
    *(float4*)&g_part_s[c][k0] = make_float4(s0, s1, s2, s3);

    float bm = fmaxf(fmaxf(m0, m1), fmaxf(m2, m3));
    #pragma unroll
    for (int o = 16; o; o >>= 1) bm = fmaxf(bm, __shfl_xor_sync(0xffffffffu, bm, o));
    __shared__ float red[8];
    if ((threadIdx.x & 31) == 0) red[threadIdx.x >> 5] = bm;
    __syncthreads();
    if (threadIdx.x == 0) {
        float t = red[0];
        #pragma unroll
        for (int i = 1; i < 8; i++) t = fmaxf(t, red[i]);
        atomicMax(&g_Mbits, enc_f(t));
    }
}

// Fixup 1: combine chunk partials with global-max rescale -> a1[k] = 1/s0[k]
__global__ __launch_bounds__(NTHR) void k_fix1() {
    const int   k = blockIdx.x * NTHR + threadIdx.x;
    const float M = dec_f(g_Mbits);
    float s = 0.f;
    #pragma unroll 4
    for (int c = 0; c < CHUNKS; c++)
        s += g_part_s[c][k] * __expf((g_part_m[c][k] - M) * INV_EPS);
    g_a[k] = 1.0f / s;
}

// Row pass: t[b] = sum_k a[k]*E[b,k]; store reciprocal (d[b]).
__global__ __launch_bounds__(NTHR) void k_rowpass(const float* __restrict__ x) {
    __shared__ float sa[KK];
    __shared__ float red[8];
    const float M = dec_f(g_Mbits);
    for (int i = threadIdx.x; i < KK; i += NTHR) sa[i] = g_a[i];
    __syncthreads();
    const float4* sa4 = (const float4*)sa;
    const int r0 = blockIdx.x * 8;
    for (int r = 0; r < 8; r++) {
        const float4* p = (const float4*)(x + (size_t)(r0 + r) * KK);
        float acc = 0.f;
        #pragma unroll
        for (int j = 0; j < 4; j++) {
            int idx = threadIdx.x + j * NTHR;
            float4 v = __ldg(p + idx);
            float4 a = sa4[idx];
            acc += a.x * __expf((v.x - M) * INV_EPS);
            acc += a.y * __expf((v.y - M) * INV_EPS);
            acc += a.z * __expf((v.z - M) * INV_EPS);
            acc += a.w * __expf((v.w - M) * INV_EPS);
        }
        float t = blockSum(acc, red);
        if (threadIdx.x == 0) g_t[r0 + r] = 1.0f / t;
    }
}

// Column pass: s[k] = sum_b d[b]*E[b,k] (d = stored reciprocal of t)
__global__ __launch_bounds__(NTHR) void k_colpass(const float* __restrict__ x) {
    const int    k0   = blockIdx.x * CPB + threadIdx.x * 4;
    const size_t base = (size_t)blockIdx.y * RPB * KK + k0;
    const float  M    = dec_f(g_Mbits);
    float s0 = 0.f, s1 = 0.f, s2 = 0.f, s3 = 0.f;
    #pragma unroll 4
    for (int r = 0; r < RPB; r++) {
        float  d = g_t[blockIdx.y * RPB + r];
        float4 v = __ldg((const float4*)(x + base + (size_t)r * KK));
        s0 += d * __expf((v.x - M) * INV_EPS);
        s1 += d * __expf((v.y - M) * INV_EPS);
        s2 += d * __expf((v.z - M) * INV_EPS);
        s3 += d * __expf((v.w - M) * INV_EPS);
    }
    *(float4*)&g_part_s[blockIdx.y][k0] = make_float4(s0, s1, s2, s3);
}

// Fixup 2: a[k] = 1 / sum_c part_s[c][k]
__global__ __launch_bounds__(NTHR) void k_fix2() {
    const int k = blockIdx.x * NTHR + threadIdx.x;
    float s = 0.f;
    #pragma unroll 4
    for (int c = 0; c < CHUNKS; c++) s += g_part_s[c][k];
    g_a[k] = 1.0f / s;
}

// Final: out[b,k] = a3[k]*E[b,k] / sum_k a3[k]*E[b,k]
__global__ __launch_bounds__(NTHR) void k_final(const float* __restrict__ x,
                                                float* __restrict__ out) {
    __shared__ float sa[KK];
    __shared__ float red[8];
    const float M = dec_f(g_Mbits);
    for (int i = threadIdx.x; i < KK; i += NTHR) sa[i] = g_a[i];
    __syncthreads();
    const float4* sa4 = (const float4*)sa;
    const int r0 = blockIdx.x * 4;
    for (int r = 0; r < 4; r++) {
        const float4* p  = (const float4*)(x   + (size_t)(r0 + r) * KK);
        float4*       po = (float4*)      (out + (size_t)(r0 + r) * KK);
        float4 v[4];
        float acc = 0.f;
        #pragma unroll
        for (int j = 0; j < 4; j++) {
            int idx = threadIdx.x + j * NTHR;
            float4 xv = __ldg(p + idx);
            float4 a  = sa4[idx];
            v[j].x = a.x * __expf((xv.x - M) * INV_EPS);
            v[j].y = a.y * __expf((xv.y - M) * INV_EPS);
            v[j].z = a.z * __expf((xv.z - M) * INV_EPS);
            v[j].w = a.w * __expf((xv.w - M) * INV_EPS);
            acc += (v[j].x + v[j].y) + (v[j].z + v[j].w);
        }
        float t   = blockSum(acc, red);
        float inv = 1.0f / t;
        #pragma unroll
        for (int j = 0; j < 4; j++) {
            int idx = threadIdx.x + j * NTHR;
            po[idx] = make_float4(v[j].x * inv, v[j].y * inv,
                                  v[j].z * inv, v[j].w * inv);
        }
    }
}

extern "C" void kernel_launch(void* const* d_in, const int* in_sizes, int n_in,
                              void* d_out, int out_size) {
    const float* x   = (const float*)d_in[0];
    float*       out = (float*)d_out;

    k_init<<<1, 1>>>();
    dim3 cg(KK / CPB, CHUNKS);              // (4, 128)
    k_pass1<<<cg, NTHR>>>(x);
    k_fix1<<<KK / NTHR, NTHR>>>();
    for (int i = 0; i < 2; i++) {           // (t1,s1) and (t2,s2)
        k_rowpass<<<BB / 8, NTHR>>>(x);
        k_colpass<<<cg, NTHR>>>(x);
        k_fix2<<<KK / NTHR, NTHR>>>();
    }
    k_final<<<BB / 4, NTHR>>>(x, out);
}

// round 2
// speedup vs baseline: 1.0088x; 1.0088x over previous
#include <cuda_runtime.h>

#define BB 16384
#define KK 4096
#define CHUNKS 128          // row-chunks for pass1
#define RPB (BB / CHUNKS)   // 128 rows per chunk
#define CPB 1024            // columns per pass1 block (256 thr * float4)
#define NTHR 256
#define FROWS 16            // rows per fused block
#define FBLK (BB / FROWS)   // 1024 fused blocks
#define OROWS 8             // rows per final block
#define INV_EPS 20.0f       // 1/0.05

// ---- scratch (device globals; no allocation) ----
__device__ float    g_part_m[CHUNKS][KK];
__device__ float    g_part_s[CHUNKS][KK];
__device__ float    g_partp[FBLK][KK];   // fused col partials (16.8 MB)
__device__ float    g_a[KK];             // a[k] = 1/s[k]
__device__ unsigned g_Mbits;             // order-encoded global max

__device__ __forceinline__ unsigned enc_f(float x) {
    unsigned u = __float_as_uint(x);
    return (u & 0x80000000u) ? ~u : (u | 0x80000000u);
}
__device__ __forceinline__ float dec_f(unsigned u) {
    return (u & 0x80000000u) ? __uint_as_float(u & 0x7FFFFFFFu)
                             : __uint_as_float(~u);
}

__device__ __forceinline__ float blockSum(float v, float* red) {
    #pragma unroll
    for (int o = 16; o; o >>= 1) v += __shfl_xor_sync(0xffffffffu, v, o);
    int w = threadIdx.x >> 5;
    if ((threadIdx.x & 31) == 0) red[w] = v;
    __syncthreads();
    if (threadIdx.x == 0) {
        float r = red[0] + red[1] + red[2] + red[3]
                + red[4] + red[5] + red[6] + red[7];
        red[0] = r;
    }
    __syncthreads();
    float r = red[0];
    __syncthreads();
    return r;
}

__global__ void k_init() { g_Mbits = 0u; }

// Pass 1: per-chunk online column (over b) sums of exp with local max,
// plus global max via atomicMax.
__global__ __launch_bounds__(NTHR) void k_pass1(const float* __restrict__ x) {
    const int    k0   = blockIdx.x * CPB + threadIdx.x * 4;
    const size_t base = (size_t)blockIdx.y * RPB * KK + k0;
    const float  NEGINF = __int_as_float(0xff800000);
    float m0 = NEGINF, m1 = NEGINF, m2 = NEGINF, m3 = NEGINF;
    float s0 = 0.f, s1 = 0.f, s2 = 0.f, s3 = 0.f;

    #pragma unroll 8
    for (int r = 0; r < RPB; r++) {
        float4 v = __ldg((const float4*)(x + base + (size_t)r * KK));
        if (v.x > m0) { s0 = s0 * __expf((m0 - v.x) * INV_EPS) + 1.0f; m0 = v.x; }
        else          { s0 += __expf((v.x - m0) * INV_EPS); }
        if (v.y > m1) { s1 = s1 * __expf((m1 - v.y) * INV_EPS) + 1.0f; m1 = v.y; }
        else          { s1 += __expf((v.y - m1) * INV_EPS); }
        if (v.z > m2) { s2 = s2 * __expf((m2 - v.z) * INV_EPS) + 1.0f; m2 = v.z; }
        else          { s2 += __expf((v.z - m2) * INV_EPS); }
        if (v.w > m3) { s3 = s3 * __expf((m3 - v.w) * INV_EPS) + 1.0f; m3 = v.w; }
        else          { s3 += __expf((v.w - m3) * INV_EPS); }
    }
    int c = blockIdx.y;
    *(float4*)&g_part_m[c][k0] = make_float4(m0, m1, m2, m3);
    *(float4*)&g_part_s[c][k0] = make_float4(s0, s1, s2, s3);

    float bm = fmaxf(fmaxf(m0, m1), fmaxf(m2, m3));
    #pragma unroll
    for (int o = 16; o; o >>= 1) bm = fmaxf(bm, __shfl_xor_sync(0xffffffffu, bm, o));
    __shared__ float red[8];
    if ((threadIdx.x & 31) == 0) red[threadIdx.x >> 5] = bm;
    __syncthreads();
    if (threadIdx.x == 0) {
        float t = red[0];
        #pragma unroll
        for (int i = 1; i < 8; i++) t = fmaxf(t, red[i]);
        atomicMax(&g_Mbits, enc_f(t));
    }
}

// Fixup 1: combine chunk partials with global-max rescale -> a1[k] = 1/s0[k]
__global__ __launch_bounds__(NTHR) void k_fix1() {
    const int   k = blockIdx.x * NTHR + threadIdx.x;
    const float M = dec_f(g_Mbits);
    float s = 0.f;
    #pragma unroll 8
    for (int c = 0; c < CHUNKS; c++)
        s += g_part_s[c][k] * __expf((g_part_m[c][k] - M) * INV_EPS);
    g_a[k] = 1.0f / s;
}

// Fused Sinkhorn iteration: one read of x computes BOTH
//   t[b] = sum_k a[k]*E[b,k]   (row sums -> d[b] = 1/t[b])
//   p[k] = sum_b d[b]*a[k]*E[b,k] = a[k]*s[k]   (per-block col partials)
// Fixup then does a_new[k] = a_old[k] / p[k].
__global__ __launch_bounds__(NTHR) void k_fused(const float* __restrict__ x) {
    __shared__ float red[8];
    const float M = dec_f(g_Mbits);
    float4 av[4];
    #pragma unroll
    for (int j = 0; j < 4; j++)
        av[j] = __ldg((const float4*)g_a + threadIdx.x + j * NTHR);

    const int r0 = blockIdx.x * FROWS;
    float4 xv[4];
    #pragma unroll
    for (int j = 0; j < 4; j++)
        xv[j] = __ldg((const float4*)(x + (size_t)r0 * KK) + threadIdx.x + j * NTHR);

    float4 pc[4];
    #pragma unroll
    for (int j = 0; j < 4; j++) pc[j] = make_float4(0.f, 0.f, 0.f, 0.f);

    for (int r = 0; r < FROWS; r++) {
        float4 w[4];
        float acc = 0.f;
        #pragma unroll
        for (int j = 0; j < 4; j++) {
            w[j].x = av[j].x * __expf((xv[j].x - M) * INV_EPS);
            w[j].y = av[j].y * __expf((xv[j].y - M) * INV_EPS);
            w[j].z = av[j].z * __expf((xv[j].z - M) * INV_EPS);
            w[j].w = av[j].w * __expf((xv[j].w - M) * INV_EPS);
            acc += (w[j].x + w[j].y) + (w[j].z + w[j].w);
        }
        // prefetch next row into xv (free after w computed) BEFORE the barrier
        if (r + 1 < FROWS) {
            #pragma unroll
            for (int j = 0; j < 4; j++)
                xv[j] = __ldg((const float4*)(x + (size_t)(r0 + r + 1) * KK)
                              + threadIdx.x + j * NTHR);
        }
        float t = blockSum(acc, red);
        float d = 1.0f / t;
        #pragma unroll
        for (int j = 0; j < 4; j++) {
            pc[j].x += d * w[j].x;
            pc[j].y += d * w[j].y;
            pc[j].z += d * w[j].z;
            pc[j].w += d * w[j].w;
        }
    }
    float4* pp = (float4*)&g_partp[blockIdx.x][0];
    #pragma unroll
    for (int j = 0; j < 4; j++) pp[threadIdx.x + j * NTHR] = pc[j];
}

// Fixup after fused iter: a[k] <- a[k] / sum_blk partp[blk][k]
__global__ __launch_bounds__(NTHR) void k_fixf() {
    const int k = blockIdx.x * NTHR + threadIdx.x;
    float s = 0.f;
    #pragma unroll 8
    for (int b = 0; b < FBLK; b++) s += g_partp[b][k];
    g_a[k] = g_a[k] / s;
}

// Final: out[b,k] = a3[k]*E[b,k] / sum_k a3[k]*E[b,k]
__global__ __launch_bounds__(NTHR) void k_final(const float* __restrict__ x,
                                                float* __restrict__ out) {
    __shared__ float red[8];
    const float M = dec_f(g_Mbits);
    float4 av[4];
    #pragma unroll
    for (int j = 0; j < 4; j++)
        av[j] = __ldg((const float4*)g_a + threadIdx.x + j * NTHR);

    const int r0 = blockIdx.x * OROWS;
    float4 xv[4];
    #pragma unroll
    for (int j = 0; j < 4; j++)
        xv[j] = __ldg((const float4*)(x + (size_t)r0 * KK) + threadIdx.x + j * NTHR);

    for (int r = 0; r < OROWS; r++) {
        float4 w[4];
        float acc = 0.f;
        #pragma unroll
        for (int j = 0; j < 4; j++) {
            w[j].x = av[j].x * __expf((xv[j].x - M) * INV_EPS);
            w[j].y = av[j].y * __expf((xv[j].y - M) * INV_EPS);
            w[j].z = av[j].z * __expf((xv[j].z - M) * INV_EPS);
            w[j].w = av[j].w * __expf((xv[j].w - M) * INV_EPS);
            acc += (w[j].x + w[j].y) + (w[j].z + w[j].w);
        }
        if (r + 1 < OROWS) {
            #pragma unroll
            for (int j = 0; j < 4; j++)
                xv[j] = __ldg((const float4*)(x + (size_t)(r0 + r + 1) * KK)
                              + threadIdx.x + j * NTHR);
        }
        float t   = blockSum(acc, red);
        float inv = 1.0f / t;
        float4* po = (float4*)(out + (size_t)(r0 + r) * KK);
        #pragma unroll
        for (int j = 0; j < 4; j++)
            po[threadIdx.x + j * NTHR] = make_float4(w[j].x * inv, w[j].y * inv,
                                                     w[j].z * inv, w[j].w * inv);
    }
}

extern "C" void kernel_launch(void* const* d_in, const int* in_sizes, int n_in,
                              void* d_out, int out_size) {
    const float* x   = (const float*)d_in[0];
    float*       out = (float*)d_out;

    k_init<<<1, 1>>>();
    dim3 cg(KK / CPB, CHUNKS);              // (4, 128)
    k_pass1<<<cg, NTHR>>>(x);
    k_fix1<<<KK / NTHR, NTHR>>>();
    for (int i = 0; i < 2; i++) {           // two fused Sinkhorn iterations
        k_fused<<<FBLK, NTHR>>>(x);
        k_fixf<<<KK / NTHR, NTHR>>>();
    }
    k_final<<<BB / OROWS, NTHR>>>(x, out);
}

// round 3
// speedup vs baseline: 1.4201x; 1.4078x over previous
#include <cuda_runtime.h>

#define BB 16384
#define KK 4096
#define CHUNKS 128          // row-chunks for pass1
#define RPB (BB / CHUNKS)   // 128 rows per chunk
#define CPB 1024            // columns per pass1 block (256 thr * float4)
#define NTHR 256
#define FROWS 16            // rows per fused block
#define FBLK (BB / FROWS)   // 1024 fused blocks
#define OROWS 8             // rows per final block
#define GRP 16              // reduction groups for two-stage fixups
#define INV_EPS 20.0f       // 1/0.05

// ---- scratch (device globals; no allocation) ----
__device__ float    g_part_m[CHUNKS][KK];
__device__ float    g_part_s[CHUNKS][KK];
__device__ float    g_partp[FBLK][KK];   // fused col partials (16.8 MB)
__device__ float    g_p2[GRP][KK];       // stage-A partials
__device__ float    g_a[KK];             // a[k]
__device__ unsigned g_Mbits;             // order-encoded global max

__device__ __forceinline__ unsigned enc_f(float x) {
    unsigned u = __float_as_uint(x);
    return (u & 0x80000000u) ? ~u : (u | 0x80000000u);
}
__device__ __forceinline__ float dec_f(unsigned u) {
    return (u & 0x80000000u) ? __uint_as_float(u & 0x7FFFFFFFu)
                             : __uint_as_float(~u);
}

__device__ __forceinline__ float blockSum(float v, float* red) {
    #pragma unroll
    for (int o = 16; o; o >>= 1) v += __shfl_xor_sync(0xffffffffu, v, o);
    int w = threadIdx.x >> 5;
    if ((threadIdx.x & 31) == 0) red[w] = v;
    __syncthreads();
    if (threadIdx.x == 0) {
        float r = red[0] + red[1] + red[2] + red[3]
                + red[4] + red[5] + red[6] + red[7];
        red[0] = r;
    }
    __syncthreads();
    float r = red[0];
    __syncthreads();
    return r;
}

__global__ void k_init() { g_Mbits = 0u; }

// Pass 1: per-chunk online column (over b) sums of exp with local max,
// plus global max via atomicMax.
__global__ __launch_bounds__(NTHR) void k_pass1(const float* __restrict__ x) {
    const int    k0   = blockIdx.x * CPB + threadIdx.x * 4;
    const size_t base = (size_t)blockIdx.y * RPB * KK + k0;
    const float  NEGINF = __int_as_float(0xff800000);
    float m0 = NEGINF, m1 = NEGINF, m2 = NEGINF, m3 = NEGINF;
    float s0 = 0.f, s1 = 0.f, s2 = 0.f, s3 = 0.f;

    #pragma unroll 8
    for (int r = 0; r < RPB; r++) {
        float4 v = __ldg((const float4*)(x + base + (size_t)r * KK));
        if (v.x > m0) { s0 = s0 * __expf((m0 - v.x) * INV_EPS) + 1.0f; m0 = v.x; }
        else          { s0 += __expf((v.x - m0) * INV_EPS); }
        if (v.y > m1) { s1 = s1 * __expf((m1 - v.y) * INV_EPS) + 1.0f; m1 = v.y; }
        else          { s1 += __expf((v.y - m1) * INV_EPS); }
        if (v.z > m2) { s2 = s2 * __expf((m2 - v.z) * INV_EPS) + 1.0f; m2 = v.z; }
        else          { s2 += __expf((v.z - m2) * INV_EPS); }
        if (v.w > m3) { s3 = s3 * __expf((m3 - v.w) * INV_EPS) + 1.0f; m3 = v.w; }
        else          { s3 += __expf((v.w - m3) * INV_EPS); }
    }
    int c = blockIdx.y;
    *(float4*)&g_part_m[c][k0] = make_float4(m0, m1, m2, m3);
    *(float4*)&g_part_s[c][k0] = make_float4(s0, s1, s2, s3);

    float bm = fmaxf(fmaxf(m0, m1), fmaxf(m2, m3));
    #pragma unroll
    for (int o = 16; o; o >>= 1) bm = fmaxf(bm, __shfl_xor_sync(0xffffffffu, bm, o));
    __shared__ float red[8];
    if ((threadIdx.x & 31) == 0) red[threadIdx.x >> 5] = bm;
    __syncthreads();
    if (threadIdx.x == 0) {
        float t = red[0];
        #pragma unroll
        for (int i = 1; i < 8; i++) t = fmaxf(t, red[i]);
        atomicMax(&g_Mbits, enc_f(t));
    }
}

// ---- two-stage fixups (wide stage A, tiny stage B) ----

// Stage A for fix1: combine 8 pass1-chunks with global-max rescale.
__global__ __launch_bounds__(NTHR) void k_fix1A() {
    const int   k = blockIdx.x * NTHR + threadIdx.x;
    const int   c0 = blockIdx.y * (CHUNKS / GRP);
    const float M = dec_f(g_Mbits);
    float s = 0.f;
    #pragma unroll
    for (int c = 0; c < CHUNKS / GRP; c++)
        s += g_part_s[c0 + c][k] * __expf((g_part_m[c0 + c][k] - M) * INV_EPS);
    g_p2[blockIdx.y][k] = s;
}

// Stage A for fixf: sum 64 fused-block partials.
__global__ __launch_bounds__(NTHR) void k_fixfA() {
    const int k  = blockIdx.x * NTHR + threadIdx.x;
    const int b0 = blockIdx.y * (FBLK / GRP);
    float s = 0.f;
    #pragma unroll 8
    for (int b = 0; b < FBLK / GRP; b++)
        s += g_partp[b0 + b][k];
    g_p2[blockIdx.y][k] = s;
}

// Stage B: combine GRP partials. mode 0: a[k]=1/s ; mode 1: a[k]/=s
__global__ __launch_bounds__(NTHR) void k_fixB(int mode) {
    const int k = blockIdx.x * NTHR + threadIdx.x;
    float s = 0.f;
    #pragma unroll
    for (int g = 0; g < GRP; g++) s += g_p2[g][k];
    g_a[k] = (mode == 0) ? (1.0f / s) : (g_a[k] / s);
}

// Fused Sinkhorn iteration: one read of x computes BOTH
//   t[b] = sum_k a[k]*E[b,k]   (row sums -> d[b] = 1/t[b])
//   p[k] = sum_b d[b]*a[k]*E[b,k]
// Fixup then does a_new[k] = a_old[k] / p[k].
__global__ __launch_bounds__(NTHR) void k_fused(const float* __restrict__ x) {
    __shared__ float red[8];
    __shared__ __align__(16) float sa[KK];
    const float M = dec_f(g_Mbits);
    #pragma unroll
    for (int j = 0; j < 4; j++)
        ((float4*)sa)[threadIdx.x + j * NTHR] =
            __ldg((const float4*)g_a + threadIdx.x + j * NTHR);
    __syncthreads();
    const float4* sa4 = (const float4*)sa;

    const int r0 = blockIdx.x * FROWS;
    float4 xv[4];
    #pragma unroll
    for (int j = 0; j < 4; j++)
        xv[j] = __ldg((const float4*)(x + (size_t)r0 * KK) + threadIdx.x + j * NTHR);

    float4 pc[4];
    #pragma unroll
    for (int j = 0; j < 4; j++) pc[j] = make_float4(0.f, 0.f, 0.f, 0.f);

    for (int r = 0; r < FROWS; r++) {
        float4 w[4];
        float acc = 0.f;
        #pragma unroll
        for (int j = 0; j < 4; j++) {
            float4 a = sa4[threadIdx.x + j * NTHR];
            w[j].x = a.x * __expf((xv[j].x - M) * INV_EPS);
            w[j].y = a.y * __expf((xv[j].y - M) * INV_EPS);
            w[j].z = a.z * __expf((xv[j].z - M) * INV_EPS);
            w[j].w = a.w * __expf((xv[j].w - M) * INV_EPS);
            acc += (w[j].x + w[j].y) + (w[j].z + w[j].w);
        }
        // prefetch next row into xv (free after w computed) BEFORE the barrier
        if (r + 1 < FROWS) {
            #pragma unroll
            for (int j = 0; j < 4; j++)
                xv[j] = __ldg((const float4*)(x + (size_t)(r0 + r + 1) * KK)
                              + threadIdx.x + j * NTHR);
        }
        float t = blockSum(acc, red);
        float d = 1.0f / t;
        #pragma unroll
        for (int j = 0; j < 4; j++) {
            pc[j].x += d * w[j].x;
            pc[j].y += d * w[j].y;
            pc[j].z += d * w[j].z;
            pc[j].w += d * w[j].w;
        }
    }
    float4* pp = (float4*)&g_partp[blockIdx.x][0];
    #pragma unroll
    for (int j = 0; j < 4; j++) pp[threadIdx.x + j * NTHR] = pc[j];
}

// Final: out[b,k] = a3[k]*E[b,k] / sum_k a3[k]*E[b,k]
__global__ __launch_bounds__(NTHR) void k_final(const float* __restrict__ x,
                                                float* __restrict__ out) {
    __shared__ float red[8];
    __shared__ __align__(16) float sa[KK];
    const float M = dec_f(g_Mbits);
    #pragma unroll
    for (int j = 0; j < 4; j++)
        ((float4*)sa)[threadIdx.x + j * NTHR] =
            __ldg((const float4*)g_a + threadIdx.x + j * NTHR);
    __syncthreads();
    const float4* sa4 = (const float4*)sa;

    const int r0 = blockIdx.x * OROWS;
    float4 xv[4];
    #pragma unroll
    for (int j = 0; j < 4; j++)
        xv[j] = __ldg((const float4*)(x + (size_t)r0 * KK) + threadIdx.x + j * NTHR);

    for (int r = 0; r < OROWS; r++) {
        float4 w[4];
        float acc = 0.f;
        #pragma unroll
        for (int j = 0; j < 4; j++) {
            float4 a = sa4[threadIdx.x + j * NTHR];
            w[j].x = a.x * __expf((xv[j].x - M) * INV_EPS);
            w[j].y = a.y * __expf((xv[j].y - M) * INV_EPS);
            w[j].z = a.z * __expf((xv[j].z - M) * INV_EPS);
            w[j].w = a.w * __expf((xv[j].w - M) * INV_EPS);
            acc += (w[j].x + w[j].y) + (w[j].z + w[j].w);
        }
        if (r + 1 < OROWS) {
            #pragma unroll
            for (int j = 0; j < 4; j++)
                xv[j] = __ldg((const float4*)(x + (size_t)(r0 + r + 1) * KK)
                              + threadIdx.x + j * NTHR);
        }
        float t   = blockSum(acc, red);
        float inv = 1.0f / t;
        float4* po = (float4*)(out + (size_t)(r0 + r) * KK);
        #pragma unroll
        for (int j = 0; j < 4; j++)
            po[threadIdx.x + j * NTHR] = make_float4(w[j].x * inv, w[j].y * inv,
                                                     w[j].z * inv, w[j].w * inv);
    }
}

extern "C" void kernel_launch(void* const* d_in, const int* in_sizes, int n_in,
                              void* d_out, int out_size) {
    const float* x   = (const float*)d_in[0];
    float*       out = (float*)d_out;

    k_init<<<1, 1>>>();
    dim3 cg(KK / CPB, CHUNKS);              // (4, 128)
    dim3 rg(KK / NTHR, GRP);                // (16, 16) stage-A grids
    k_pass1<<<cg, NTHR>>>(x);
    k_fix1A<<<rg, NTHR>>>();
    k_fixB<<<KK / NTHR, NTHR>>>(0);
    for (int i = 0; i < 2; i++) {           // two fused Sinkhorn iterations
        k_fused<<<FBLK, NTHR>>>(x);
        k_fixfA<<<rg, NTHR>>>();
        k_fixB<<<KK / NTHR, NTHR>>>(1);
    }
    k_final<<<BB / OROWS, NTHR>>>(x, out);
}

// round 4
// speedup vs baseline: 1.4303x; 1.0072x over previous
#include <cuda_runtime.h>

#define BB 16384
#define KK 4096
#define CHUNKS 128          // row-chunks for pass1
#define RPB (BB / CHUNKS)   // 128 rows per chunk
#define CPB 1024            // columns per pass1 block (256 thr * float4)
#define NTHR 256
#define FROWS 16            // rows per fused block
#define FBLK (BB / FROWS)   // 1024 fused blocks
#define OROWS 8             // rows per final block
#define GRP 16              // reduction groups for two-stage fixups
#define INV_EPS 20.0f       // 1/0.05

// ---- scratch (device globals; no allocation) ----
__device__ float    g_part_m[CHUNKS][KK];
__device__ float    g_part_s[CHUNKS][KK];
__device__ float    g_partp[FBLK][KK];   // fused col partials (16.8 MB)
__device__ float    g_p2[GRP][KK];       // stage-A partials
__device__ float    g_a[KK];             // a[k]
__device__ unsigned g_Mbits;             // order-encoded global max

__device__ __forceinline__ unsigned enc_f(float x) {
    unsigned u = __float_as_uint(x);
    return (u & 0x80000000u) ? ~u : (u | 0x80000000u);
}
__device__ __forceinline__ float dec_f(unsigned u) {
    return (u & 0x80000000u) ? __uint_as_float(u & 0x7FFFFFFFu)
                             : __uint_as_float(~u);
}

// Single-barrier block row-sum: shuffle tree, lane0 -> slot[parity][wid],
// one __syncthreads, then EVERY thread sums the 8 slots (fixed order ->
// deterministic, identical in all threads). Double-buffered by parity so
// the next row's writes never race this row's reads.
__device__ __forceinline__ float rowReduce(float v, float (*slot)[8], int par) {
    #pragma unroll
    for (int o = 16; o; o >>= 1) v += __shfl_xor_sync(0xffffffffu, v, o);
    if ((threadIdx.x & 31) == 0) slot[par][threadIdx.x >> 5] = v;
    __syncthreads();
    float t = ((slot[par][0] + slot[par][1]) + (slot[par][2] + slot[par][3]))
            + ((slot[par][4] + slot[par][5]) + (slot[par][6] + slot[par][7]));
    return t;
}

__global__ void k_init() { g_Mbits = 0u; }

// Pass 1: per-chunk online column (over b) sums of exp with local max,
// plus global max via atomicMax.
__global__ __launch_bounds__(NTHR) void k_pass1(const float* __restrict__ x) {
    const int    k0   = blockIdx.x * CPB + threadIdx.x * 4;
    const size_t base = (size_t)blockIdx.y * RPB * KK + k0;
    const float  NEGINF = __int_as_float(0xff800000);
    float m0 = NEGINF, m1 = NEGINF, m2 = NEGINF, m3 = NEGINF;
    float s0 = 0.f, s1 = 0.f, s2 = 0.f, s3 = 0.f;

    #pragma unroll 8
    for (int r = 0; r < RPB; r++) {
        float4 v = __ldg((const float4*)(x + base + (size_t)r * KK));
        if (v.x > m0) { s0 = s0 * __expf((m0 - v.x) * INV_EPS) + 1.0f; m0 = v.x; }
        else          { s0 += __expf((v.x - m0) * INV_EPS); }
        if (v.y > m1) { s1 = s1 * __expf((m1 - v.y) * INV_EPS) + 1.0f; m1 = v.y; }
        else          { s1 += __expf((v.y - m1) * INV_EPS); }
        if (v.z > m2) { s2 = s2 * __expf((m2 - v.z) * INV_EPS) + 1.0f; m2 = v.z; }
        else          { s2 += __expf((v.z - m2) * INV_EPS); }
        if (v.w > m3) { s3 = s3 * __expf((m3 - v.w) * INV_EPS) + 1.0f; m3 = v.w; }
        else          { s3 += __expf((v.w - m3) * INV_EPS); }
    }
    int c = blockIdx.y;
    *(float4*)&g_part_m[c][k0] = make_float4(m0, m1, m2, m3);
    *(float4*)&g_part_s[c][k0] = make_float4(s0, s1, s2, s3);

    float bm = fmaxf(fmaxf(m0, m1), fmaxf(m2, m3));
    #pragma unroll
    for (int o = 16; o; o >>= 1) bm = fmaxf(bm, __shfl_xor_sync(0xffffffffu, bm, o));
    __shared__ float red[8];
    if ((threadIdx.x & 31) == 0) red[threadIdx.x >> 5] = bm;
    __syncthreads();
    if (threadIdx.x == 0) {
        float t = red[0];
        #pragma unroll
        for (int i = 1; i < 8; i++) t = fmaxf(t, red[i]);
        atomicMax(&g_Mbits, enc_f(t));
    }
}

// ---- two-stage fixups (wide stage A, tiny stage B) ----

__global__ __launch_bounds__(NTHR) void k_fix1A() {
    const int   k = blockIdx.x * NTHR + threadIdx.x;
    const int   c0 = blockIdx.y * (CHUNKS / GRP);
    const float M = dec_f(g_Mbits);
    float s = 0.f;
    #pragma unroll
    for (int c = 0; c < CHUNKS / GRP; c++)
        s += g_part_s[c0 + c][k] * __expf((g_part_m[c0 + c][k] - M) * INV_EPS);
    g_p2[blockIdx.y][k] = s;
}

__global__ __launch_bounds__(NTHR) void k_fixfA() {
    const int k  = blockIdx.x * NTHR + threadIdx.x;
    const int b0 = blockIdx.y * (FBLK / GRP);
    float s = 0.f;
    #pragma unroll 8
    for (int b = 0; b < FBLK / GRP; b++)
        s += g_partp[b0 + b][k];
    g_p2[blockIdx.y][k] = s;
}

// Stage B: combine GRP partials. mode 0: a[k]=1/s ; mode 1: a[k]/=s
__global__ __launch_bounds__(NTHR) void k_fixB(int mode) {
    const int k = blockIdx.x * NTHR + threadIdx.x;
    float s = 0.f;
    #pragma unroll
    for (int g = 0; g < GRP; g++) s += g_p2[g][k];
    g_a[k] = (mode == 0) ? (1.0f / s) : (g_a[k] / s);
}

// Fused Sinkhorn iteration: one read of x computes BOTH
//   t[b] = sum_k a[k]*E[b,k]   (row sums -> d[b] = 1/t[b])
//   p[k] = sum_b d[b]*a[k]*E[b,k]
__global__ __launch_bounds__(NTHR) void k_fused(const float* __restrict__ x) {
    __shared__ float slot[2][8];
    __shared__ __align__(16) float sa[KK];
    const float M = dec_f(g_Mbits);
    #pragma unroll
    for (int j = 0; j < 4; j++)
        ((float4*)sa)[threadIdx.x + j * NTHR] =
            __ldg((const float4*)g_a + threadIdx.x + j * NTHR);
    __syncthreads();
    const float4* sa4 = (const float4*)sa;

    const int r0 = blockIdx.x * FROWS;
    float4 xv[4];
    #pragma unroll
    for (int j = 0; j < 4; j++)
        xv[j] = __ldg((const float4*)(x + (size_t)r0 * KK) + threadIdx.x + j * NTHR);

    float4 pc[4];
    #pragma unroll
    for (int j = 0; j < 4; j++) pc[j] = make_float4(0.f, 0.f, 0.f, 0.f);

    for (int r = 0; r < FROWS; r++) {
        float4 w[4];
        float acc = 0.f;
        #pragma unroll
        for (int j = 0; j < 4; j++) {
            float4 a = sa4[threadIdx.x + j * NTHR];
            w[j].x = a.x * __expf((xv[j].x - M) * INV_EPS);
            w[j].y = a.y * __expf((xv[j].y - M) * INV_EPS);
            w[j].z = a.z * __expf((xv[j].z - M) * INV_EPS);
            w[j].w = a.w * __expf((xv[j].w - M) * INV_EPS);
            acc += (w[j].x + w[j].y) + (w[j].z + w[j].w);
        }
        // prefetch next row (xv regs free) before the reduction barrier
        if (r + 1 < FROWS) {
            #pragma unroll
            for (int j = 0; j < 4; j++)
                xv[j] = __ldg((const float4*)(x + (size_t)(r0 + r + 1) * KK)
                              + threadIdx.x + j * NTHR);
        }
        float t = rowReduce(acc, slot, r & 1);
        float d = 1.0f / t;
        #pragma unroll
        for (int j = 0; j < 4; j++) {
            pc[j].x += d * w[j].x;
            pc[j].y += d * w[j].y;
            pc[j].z += d * w[j].z;
            pc[j].w += d * w[j].w;
        }
    }
    float4* pp = (float4*)&g_partp[blockIdx.x][0];
    #pragma unroll
    for (int j = 0; j < 4; j++) pp[threadIdx.x + j * NTHR] = pc[j];
}

// Final: out[b,k] = a3[k]*E[b,k] / sum_k a3[k]*E[b,k]
__global__ __launch_bounds__(NTHR) void k_final(const float* __restrict__ x,
                                                float* __restrict__ out) {
    __shared__ float slot[2][8];
    __shared__ __align__(16) float sa[KK];
    const float M = dec_f(g_Mbits);
    #pragma unroll
    for (int j = 0; j < 4; j++)
        ((float4*)sa)[threadIdx.x + j * NTHR] =
            __ldg((const float4*)g_a + threadIdx.x + j * NTHR);
    __syncthreads();
    const float4* sa4 = (const float4*)sa;

    const int r0 = blockIdx.x * OROWS;
    float4 xv[4];
    #pragma unroll
    for (int j = 0; j < 4; j++)
        xv[j] = __ldg((const float4*)(x + (size_t)r0 * KK) + threadIdx.x + j * NTHR);

    for (int r = 0; r < OROWS; r++) {
        float4 w[4];
        float acc = 0.f;
        #pragma unroll
        for (int j = 0; j < 4; j++) {
            float4 a = sa4[threadIdx.x + j * NTHR];
            w[j].x = a.x * __expf((xv[j].x - M) * INV_EPS);
            w[j].y = a.y * __expf((xv[j].y - M) * INV_EPS);
            w[j].z = a.z * __expf((xv[j].z - M) * INV_EPS);
            w[j].w = a.w * __expf((xv[j].w - M) * INV_EPS);
            acc += (w[j].x + w[j].y) + (w[j].z + w[j].w);
        }
        if (r + 1 < OROWS) {
            #pragma unroll
            for (int j = 0; j < 4; j++)
                xv[j] = __ldg((const float4*)(x + (size_t)(r0 + r + 1) * KK)
                              + threadIdx.x + j * NTHR);
        }
        float t   = rowReduce(acc, slot, r & 1);
        float inv = 1.0f / t;
        float4* po = (float4*)(out + (size_t)(r0 + r) * KK);
        #pragma unroll
        for (int j = 0; j < 4; j++)
            po[threadIdx.x + j * NTHR] = make_float4(w[j].x * inv, w[j].y * inv,
                                                     w[j].z * inv, w[j].w * inv);
    }
}

extern "C" void kernel_launch(void* const* d_in, const int* in_sizes, int n_in,
                              void* d_out, int out_size) {
    const float* x   = (const float*)d_in[0];
    float*       out = (float*)d_out;

    k_init<<<1, 1>>>();
    dim3 cg(KK / CPB, CHUNKS);              // (4, 128)
    dim3 rg(KK / NTHR, GRP);                // (16, 16) stage-A grids
    k_pass1<<<cg, NTHR>>>(x);
    k_fix1A<<<rg, NTHR>>>();
    k_fixB<<<KK / NTHR, NTHR>>>(0);
    for (int i = 0; i < 2; i++) {           // two fused Sinkhorn iterations
        k_fused<<<FBLK, NTHR>>>(x);
        k_fixfA<<<rg, NTHR>>>();
        k_fixB<<<KK / NTHR, NTHR>>>(1);
    }
    k_final<<<BB / OROWS, NTHR>>>(x, out);
}